// round 4
// baseline (speedup 1.0000x reference)
#include <cuda_runtime.h>
#include <cuda_bf16.h>

// Embedding gather: out[s, :] = weights[x[s], :]
// x: [8192] int32, weights: [49408, 768] fp32, out: [8192, 768] fp32
// Geometry: U=4 rows/CTA (grid=2048 restores occupancy), MLP=4 per thread.
// Weights loads use evict-first (.cs): zero-reuse stream, keep L2 for output.

#define SEQ 8192
#define DIM 768
#define VEC (DIM / 4)   // 192 float4 per row
#define U   4           // rows per CTA

__global__ void __launch_bounds__(VEC) embed_gather_kernel(
    const int* __restrict__ x,
    const float4* __restrict__ weights,   // [VOCAB, VEC]
    float4* __restrict__ out)             // [SEQ, VEC]
{
    const int t  = threadIdx.x;
    const int s0 = blockIdx.x * U;

    // One vectorized 16B index load (s0*4 bytes is 16B-aligned since U=4)
    const int4 r4 = *reinterpret_cast<const int4*>(x + s0);
    const int rows[U] = { r4.x, r4.y, r4.z, r4.w };

    // 4 independent 16B gathers in flight per thread, evict-first
    float4 v[U];
#pragma unroll
    for (int u = 0; u < U; u++)
        v[u] = __ldcs(&weights[(size_t)rows[u] * VEC + t]);

#pragma unroll
    for (int u = 0; u < U; u++)
        out[(size_t)(s0 + u) * VEC + t] = v[u];
}

extern "C" void kernel_launch(void* const* d_in, const int* in_sizes, int n_in,
                              void* d_out, int out_size) {
    const int*    x = (const int*)d_in[0];
    const float4* w = (const float4*)d_in[1];
    float4*       o = (float4*)d_out;
    embed_gather_kernel<<<SEQ / U, VEC>>>(x, w, o);
}

// round 5
// speedup vs baseline: 1.2657x; 1.2657x over previous
#include <cuda_runtime.h>
#include <cuda_bf16.h>
#include <cstdint>

// Embedding gather via bulk-DMA: out[s,:] = weights[x[s],:]
// x: [8192] int32, weights: [49408, 768] fp32, out: [8192, 768] fp32
// Row = 3072 bytes. Each CTA: 1 driver warp, 8 rows in flight via
// cp.async.bulk (global->shared, mbarrier) then cp.async.bulk (shared->global,
// bulk_group). Bypasses the L1tex MSHR concurrency cap that pinned the LDG
// version at ~2.4 TB/s.

#define SEQ       8192
#define ROW_BYTES 3072
#define RPC       8            // rows per CTA (== ring depth, no reuse)
#define GRID      (SEQ / RPC)  // 1024

__device__ __forceinline__ uint32_t smem_u32(const void* p) {
    uint32_t a;
    asm("{ .reg .u64 t; cvta.to.shared.u64 t, %1; cvt.u32.u64 %0, t; }"
        : "=r"(a) : "l"(p));
    return a;
}

__global__ void __launch_bounds__(32) embed_bulk_kernel(
    const int* __restrict__ x,
    const char* __restrict__ weights,
    char* __restrict__ out)
{
    __shared__ __align__(128) char buf[RPC][ROW_BYTES];
    __shared__ __align__(8)  unsigned long long mbar[RPC];

    if (threadIdx.x != 0) return;   // single driver thread; CTA stays alive

    const int s0 = blockIdx.x * RPC;
    const uint32_t mbar0 = smem_u32(&mbar[0]);
    const uint32_t buf0  = smem_u32(&buf[0][0]);

    // Init mbarriers (same thread uses them; fence orders generic init vs async proxy)
#pragma unroll
    for (int i = 0; i < RPC; i++)
        asm volatile("mbarrier.init.shared.b64 [%0], 1;" :: "r"(mbar0 + i * 8) : "memory");
    asm volatile("fence.proxy.async.shared::cta;" ::: "memory");

    // Issue all row loads (8 x 3072B in flight)
#pragma unroll
    for (int i = 0; i < RPC; i++) {
        const int row = __ldg(&x[s0 + i]);
        const uint32_t mb = mbar0 + i * 8;
        asm volatile("mbarrier.arrive.expect_tx.shared.b64 _, [%0], %1;"
                     :: "r"(mb), "r"((uint32_t)ROW_BYTES) : "memory");
        asm volatile(
            "cp.async.bulk.shared::cta.global.mbarrier::complete_tx::bytes "
            "[%0], [%1], %2, [%3];"
            :: "r"(buf0 + i * ROW_BYTES),
               "l"(weights + (size_t)row * ROW_BYTES),
               "r"((uint32_t)ROW_BYTES),
               "r"(mb)
            : "memory");
    }

    // Drain in order: wait each load, then bulk-store the row out
#pragma unroll
    for (int i = 0; i < RPC; i++) {
        const uint32_t mb = mbar0 + i * 8;
        uint32_t done;
        asm volatile(
            "{\n\t"
            ".reg .pred p;\n\t"
            "mbarrier.try_wait.parity.acquire.cta.shared::cta.b64 p, [%1], 0;\n\t"
            "selp.b32 %0, 1, 0, p;\n\t"
            "}" : "=r"(done) : "r"(mb) : "memory");
        if (!done) {
            asm volatile(
                "{\n\t"
                ".reg .pred P1;\n\t"
                "WL_%=:\n\t"
                "mbarrier.try_wait.parity.acquire.cta.shared::cta.b64 P1, [%0], 0, 0x989680;\n\t"
                "@P1 bra.uni WD_%=;\n\t"
                "bra.uni WL_%=;\n\t"
                "WD_%=:\n\t"
                "}" :: "r"(mb) : "memory");
        }
        asm volatile("fence.proxy.async.shared::cta;" ::: "memory");
        asm volatile(
            "cp.async.bulk.global.shared::cta.bulk_group [%0], [%1], %2;"
            :: "l"(out + (size_t)(s0 + i) * ROW_BYTES),
               "r"(buf0 + i * ROW_BYTES),
               "r"((uint32_t)ROW_BYTES)
            : "memory");
        asm volatile("cp.async.bulk.commit_group;" ::: "memory");
    }

    // All stores must complete before CTA exit
    asm volatile("cp.async.bulk.wait_group 0;" ::: "memory");
}

extern "C" void kernel_launch(void* const* d_in, const int* in_sizes, int n_in,
                              void* d_out, int out_size) {
    const int*  x = (const int*)d_in[0];
    const char* w = (const char*)d_in[1];
    char*       o = (char*)d_out;
    embed_bulk_kernel<<<GRID, 32>>>(x, w, o);
}